// round 16
// baseline (speedup 1.0000x reference)
#include <cuda_runtime.h>

#define NROWS 8192
#define NDIM  512
#define ND4   128      // NDIM/4
#define NTOP  100
#define NBLK  128
#define NTHR  1024
#define NBIN  4096
#define CAP   1536

__device__ float4 g_s4v[ND4];          // column sum (zeroed by K3 each run)
__device__ float  g_rinv[NROWS];
__device__ unsigned int g_key[NROWS];

// ============================================================================
// K1: per-row 1/||x|| + column-sum of unit rows -> 512 REDs into g_s4v.
// Triggers PDL completion early so K2 can start launching.
// ============================================================================
__global__ void __launch_bounds__(NTHR, 1) k1(const float4* __restrict__ x4) {
    __shared__ float4 sacc[16 * ND4];        // 32 KB
    __shared__ float  psum[2 * NDIM];        // 4 KB
    float* saccf = (float*)sacc;

    const int t    = threadIdx.x;
    const int wid  = t >> 5;
    const int lane = t & 31;
    const int row0 = blockIdx.x * 64 + wid * 2;

    const float4* r0 = x4 + (size_t)row0 * ND4;
    const float4* r1 = r0 + ND4;
    float4 v0[4], v1[4];
    #pragma unroll
    for (int k = 0; k < 4; ++k) v0[k] = r0[lane + 32 * k];
    #pragma unroll
    for (int k = 0; k < 4; ++k) v1[k] = r1[lane + 32 * k];

#if __CUDA_ARCH__ >= 900
    cudaTriggerProgrammaticLaunchCompletion();   // let K2 blocks start
#endif

    float sq0 = 0.f, sq1 = 0.f;
    #pragma unroll
    for (int k = 0; k < 4; ++k) {
        sq0 += v0[k].x*v0[k].x + v0[k].y*v0[k].y + v0[k].z*v0[k].z + v0[k].w*v0[k].w;
        sq1 += v1[k].x*v1[k].x + v1[k].y*v1[k].y + v1[k].z*v1[k].z + v1[k].w*v1[k].w;
    }
    #pragma unroll
    for (int o = 16; o; o >>= 1) {
        sq0 += __shfl_xor_sync(0xffffffffu, sq0, o);
        sq1 += __shfl_xor_sync(0xffffffffu, sq1, o);
    }
    float rinv0 = rsqrtf(sq0);   // rel err ~2e-7 << rank-100 boundary gap
    float rinv1 = rsqrtf(sq1);
    if (lane == 0) *(float2*)&g_rinv[row0] = make_float2(rinv0, rinv1);

    float4 acc[4];
    #pragma unroll
    for (int k = 0; k < 4; ++k) {
        acc[k].x = fmaf(v0[k].x, rinv0, v1[k].x * rinv1);
        acc[k].y = fmaf(v0[k].y, rinv0, v1[k].y * rinv1);
        acc[k].z = fmaf(v0[k].z, rinv0, v1[k].z * rinv1);
        acc[k].w = fmaf(v0[k].w, rinv0, v1[k].w * rinv1);
    }
    if (wid >= 16) {
        #pragma unroll
        for (int k = 0; k < 4; ++k) sacc[(wid - 16) * ND4 + lane + 32 * k] = acc[k];
    }
    __syncthreads();
    if (wid < 16) {
        #pragma unroll
        for (int k = 0; k < 4; ++k) {
            float4 o = sacc[wid * ND4 + lane + 32 * k];
            acc[k].x += o.x; acc[k].y += o.y; acc[k].z += o.z; acc[k].w += o.w;
            sacc[wid * ND4 + lane + 32 * k] = acc[k];
        }
    }
    __syncthreads();
    {
        int d = t & (NDIM - 1);
        int g = t >> 9;
        float s = 0.f;
        #pragma unroll
        for (int b = 0; b < 8; ++b) s += saccf[(g * 8 + b) * NDIM + d];
        psum[g * NDIM + d] = s;
    }
    __syncthreads();
    if (t < NDIM) atomicAdd((float*)g_s4v + t, psum[t] + psum[NDIM + t]);
}

// ============================================================================
// K2 (PDL): preload x from L2, THEN wait for K1, then dot with s -> keys.
// ============================================================================
__global__ void __launch_bounds__(NTHR, 1) k2(const float4* __restrict__ x4) {
    const int t    = threadIdx.x;
    const int wid  = t >> 5;
    const int lane = t & 31;
    const int row0 = blockIdx.x * 64 + wid * 2;

    // preload x BEFORE the dependency sync (overlaps K1's tail)
    const float4* r0 = x4 + (size_t)row0 * ND4;
    const float4* r1 = r0 + ND4;
    float4 a[4], b[4];
    #pragma unroll
    for (int k = 0; k < 4; ++k) a[k] = r0[lane + 32 * k];
    #pragma unroll
    for (int k = 0; k < 4; ++k) b[k] = r1[lane + 32 * k];

#if __CUDA_ARCH__ >= 900
    cudaTriggerProgrammaticLaunchCompletion();   // let K3 blocks start
    cudaGridDependencySynchronize();             // wait: g_s4v complete
#endif

    float4 sv[4];
    #pragma unroll
    for (int k = 0; k < 4; ++k) sv[k] = g_s4v[lane + 32 * k];

    float dot0 = 0.f, dot1 = 0.f;
    #pragma unroll
    for (int k = 0; k < 4; ++k) {
        dot0 = fmaf(a[k].x, sv[k].x, dot0); dot0 = fmaf(a[k].y, sv[k].y, dot0);
        dot0 = fmaf(a[k].z, sv[k].z, dot0); dot0 = fmaf(a[k].w, sv[k].w, dot0);
        dot1 = fmaf(b[k].x, sv[k].x, dot1); dot1 = fmaf(b[k].y, sv[k].y, dot1);
        dot1 = fmaf(b[k].z, sv[k].z, dot1); dot1 = fmaf(b[k].w, sv[k].w, dot1);
    }
    #pragma unroll
    for (int o = 16; o; o >>= 1) {
        dot0 += __shfl_down_sync(0xffffffffu, dot0, o);
        dot1 += __shfl_down_sync(0xffffffffu, dot1, o);
    }
    if (lane == 0) {
        float2 ri = *(const float2*)&g_rinv[row0];
        unsigned int u0 = __float_as_uint(dot0 * ri.x);
        unsigned int u1 = __float_as_uint(dot1 * ri.y);
        u0 = (u0 & 0x80000000u) ? ~u0 : (u0 | 0x80000000u);
        u1 = (u1 & 0x80000000u) ? ~u1 : (u1 | 0x80000000u);
        *(uint2*)&g_key[row0] = make_uint2(u0, u1);
    }
}

// ============================================================================
// K3 (PDL): zero hist BEFORE sync; then keys->regs, smem hist, boundary bin,
// collect, exact stable rank; block b writes rank-b row + index.
// Block 0 re-zeros g_s4v (replay invariant; K2 already consumed it).
// ============================================================================
__global__ void __launch_bounds__(NTHR, 1) k3(const float4* __restrict__ x4,
                                              float* __restrict__ out,
                                              float4* __restrict__ out4,
                                              int out_size) {
    __shared__ int4 hist4[NBIN / 4];                 // 16 KB
    __shared__ unsigned int ckey[CAP];               // 6 KB
    __shared__ int cidx[CAP];                        // 6 KB
    __shared__ int swarp[32];
    __shared__ int sh_B, sh_ncand, s_row;
    int* hist = (int*)hist4;

    const int t    = threadIdx.x;
    const int wid  = t >> 5;
    const int lane = t & 31;

    // pre-sync work: zero histogram + counters
    #pragma unroll
    for (int j = 0; j < NBIN / NTHR; ++j) hist[t + NTHR * j] = 0;
    if (t == 0) sh_ncand = 0;
    __syncthreads();

#if __CUDA_ARCH__ >= 900
    cudaGridDependencySynchronize();             // wait: keys complete
#endif

    uint4 ka = ((const uint4*)g_key)[t];
    uint4 kb = ((const uint4*)g_key)[t + 1024];
    unsigned int keys[8] = {ka.x, ka.y, ka.z, ka.w, kb.x, kb.y, kb.z, kb.w};

    #pragma unroll
    for (int j = 0; j < 8; ++j) atomicAdd(&hist[keys[j] >> 20], 1);
    __syncthreads();

    // scan 4096 bins (4/thread) for boundary bin B
    int4 hv = hist4[t];
    int hh[4] = {hv.x, hv.y, hv.z, hv.w};
    int lsum = hh[0] + hh[1] + hh[2] + hh[3];
    int v = lsum;
    #pragma unroll
    for (int o = 1; o < 32; o <<= 1) {
        int u = __shfl_up_sync(0xffffffffu, v, o);
        if (lane >= o) v += u;
    }
    if (lane == 31) swarp[wid] = v;
    __syncthreads();
    if (t < 32) {
        int w = swarp[t];
        int vv = w;
        #pragma unroll
        for (int o = 1; o < 32; o <<= 1) {
            int u = __shfl_up_sync(0xffffffffu, vv, o);
            if (lane >= o) vv += u;
        }
        swarp[t] = vv - w;
    }
    __syncthreads();
    {
        int c = swarp[wid] + (v - lsum);
        #pragma unroll
        for (int i = 0; i < 4; ++i) {
            int c2 = c + hh[i];
            if (c < NTOP && c2 >= NTOP) sh_B = 4 * t + i;
            c = c2;
        }
    }
    __syncthreads();
    unsigned int B = (unsigned int)sh_B;

    // collect candidates (warp-aggregated append)
    #pragma unroll
    for (int j = 0; j < 8; ++j) {
        bool hit = (keys[j] >> 20) <= B;
        unsigned int m = __ballot_sync(0xffffffffu, hit);
        if (m) {
            int cnt = __popc(m);
            int leader = __ffs(m) - 1;
            int base = 0;
            if (lane == leader) base = atomicAdd(&sh_ncand, cnt);
            base = __shfl_sync(0xffffffffu, base, leader);
            if (hit) {
                int p = base + __popc(m & ((1u << lane) - 1u));
                if (p < CAP) {
                    ckey[p] = keys[j];
                    cidx[p] = (j < 4) ? (4 * t + j) : (4096 + 4 * t + (j - 4));
                }
            }
        }
    }
    __syncthreads();
    int nc = sh_ncand < CAP ? sh_ncand : CAP;

    if (t < nc) {
        unsigned int mk = ckey[t];
        int mi = cidx[t];
        int rank = 0;
        for (int j = 0; j < nc; ++j)
            rank += (ckey[j] < mk || (ckey[j] == mk && cidx[j] < mi)) ? 1 : 0;
        if (rank == blockIdx.x) s_row = mi;
    }
    __syncthreads();

    int row = s_row;
    if (t < ND4) {
        int e = blockIdx.x * ND4 + t;
        if (4 * e + 4 <= out_size)
            out4[e] = x4[(size_t)row * ND4 + t];
    }
    if (t == 0 && NTOP * NDIM + blockIdx.x < out_size)
        out[NTOP * NDIM + blockIdx.x] = (float)row;

    if (blockIdx.x == 0 && t < ND4)
        g_s4v[t] = make_float4(0.f, 0.f, 0.f, 0.f);
}

extern "C" void kernel_launch(void* const* d_in, const int* in_sizes, int n_in,
                              void* d_out, int out_size) {
    const float4* x4 = (const float4*)d_in[0];
    float* out = (float*)d_out;
    float4* out4 = (float4*)d_out;

    k1<<<NBLK, NTHR>>>(x4);

    cudaLaunchAttribute pdl[1];
    pdl[0].id = cudaLaunchAttributeProgrammaticStreamSerialization;
    pdl[0].val.programmaticStreamSerializationAllowed = 1;

    {
        cudaLaunchConfig_t cfg = {};
        cfg.gridDim = dim3(NBLK); cfg.blockDim = dim3(NTHR);
        cfg.stream = 0; cfg.attrs = pdl; cfg.numAttrs = 1;
        cudaLaunchKernelEx(&cfg, k2, x4);
    }
    {
        cudaLaunchConfig_t cfg = {};
        cfg.gridDim = dim3(NTOP); cfg.blockDim = dim3(NTHR);
        cfg.stream = 0; cfg.attrs = pdl; cfg.numAttrs = 1;
        cudaLaunchKernelEx(&cfg, k3, x4, out, out4, out_size);
    }
}